// round 15
// baseline (speedup 1.0000x reference)
#include <cuda_runtime.h>
#include <cuda_bf16.h>
#include <math.h>
#include <stdint.h>

#define BATCH 512
#define DIMD 256
#define MMEM 131072
#define NCLS 100
#define KTOP 256

// ------------- scratch globals (no allocation allowed) -------------
__device__ unsigned short g_simsb[(size_t)BATCH * MMEM];    // bf16 approx sims, 134MB
__device__ unsigned short g_qnb[BATCH * DIMD];              // bf16 normalized queries
__device__ unsigned short g_knb[(size_t)MMEM * DIMD];       // bf16 normalized keys, 67MB
__device__ float g_rnx[BATCH];
__device__ float g_rnk[MMEM];

// ------------- helpers -------------
__device__ __forceinline__ unsigned enc_f(float f) {
    unsigned u = __float_as_uint(f);
    return (u & 0x80000000u) ? ~u : (u | 0x80000000u);
}
__device__ __forceinline__ uint32_t smem_u32(const void* p) {
    uint32_t a;
    asm("{ .reg .u64 t; cvta.to.shared.u64 t, %1; cvt.u32.u64 %0, t; }" : "=r"(a) : "l"(p));
    return a;
}
__device__ __forceinline__ void cp16(uint32_t saddr, const void* g) {
    asm volatile("cp.async.cg.shared.global [%0], [%1], 16;" :: "r"(saddr), "l"(g));
}
#define CP_COMMIT() asm volatile("cp.async.commit_group;" ::: "memory")
#define CP_WAIT1()  asm volatile("cp.async.wait_group 1;" ::: "memory")
#define CP_WAIT0()  asm volatile("cp.async.wait_group 0;" ::: "memory")

__device__ __forceinline__ void ldsm_x4(uint32_t* r, uint32_t addr) {
    asm volatile("ldmatrix.sync.aligned.m8n8.x4.shared.b16 {%0,%1,%2,%3}, [%4];"
                 : "=r"(r[0]), "=r"(r[1]), "=r"(r[2]), "=r"(r[3]) : "r"(addr));
}
__device__ __forceinline__ void mma16816(float* d, const uint32_t* a, const uint32_t* b) {
    asm volatile(
        "mma.sync.aligned.m16n8k16.row.col.f32.bf16.bf16.f32 "
        "{%0,%1,%2,%3}, {%4,%5,%6,%7}, {%8,%9}, {%0,%1,%2,%3};"
        : "+f"(d[0]), "+f"(d[1]), "+f"(d[2]), "+f"(d[3])
        : "r"(a[0]), "r"(a[1]), "r"(a[2]), "r"(a[3]), "r"(b[0]), "r"(b[1]));
}

// ------------- 1. prep: reciprocal norms + normalized bf16 conversion -------------
__global__ void prep_kernel(const float* __restrict__ x, const float* __restrict__ mk) {
    int warp = (blockIdx.x * blockDim.x + threadIdx.x) >> 5;
    int lane = threadIdx.x & 31;
    if (warp >= BATCH + MMEM) return;
    bool isX = (warp < BATCH);
    int row = isX ? warp : (warp - BATCH);
    const float* ptr = isX ? (x + (size_t)row * DIMD) : (mk + (size_t)row * DIMD);
    const float4* p4 = (const float4*)ptr;
    float4 v0 = p4[lane];
    float4 v1 = p4[lane + 32];
    float s = v0.x * v0.x + v0.y * v0.y + v0.z * v0.z + v0.w * v0.w
            + v1.x * v1.x + v1.y * v1.y + v1.z * v1.z + v1.w * v1.w;
#pragma unroll
    for (int o = 16; o; o >>= 1) s += __shfl_xor_sync(0xffffffffu, s, o);
    float rn = 1.0f / (sqrtf(s) + 1e-12f);
    rn = __shfl_sync(0xffffffffu, rn, 0);
    if (lane == 0) {
        if (isX) g_rnx[row] = rn; else g_rnk[row] = rn;
    }
    unsigned short* dst = isX ? (g_qnb + (size_t)row * DIMD) : (g_knb + (size_t)row * DIMD);
    {
        unsigned a = __bfloat16_as_ushort(__float2bfloat16(v0.x * rn)) |
                     ((unsigned)__bfloat16_as_ushort(__float2bfloat16(v0.y * rn)) << 16);
        unsigned b = __bfloat16_as_ushort(__float2bfloat16(v0.z * rn)) |
                     ((unsigned)__bfloat16_as_ushort(__float2bfloat16(v0.w * rn)) << 16);
        *(uint2*)(dst + lane * 4) = make_uint2(a, b);
    }
    {
        unsigned a = __bfloat16_as_ushort(__float2bfloat16(v1.x * rn)) |
                     ((unsigned)__bfloat16_as_ushort(__float2bfloat16(v1.y * rn)) << 16);
        unsigned b = __bfloat16_as_ushort(__float2bfloat16(v1.z * rn)) |
                     ((unsigned)__bfloat16_as_ushort(__float2bfloat16(v1.w * rn)) << 16);
        *(uint2*)(dst + (lane + 32) * 4) = make_uint2(a, b);
    }
}

// ------------- 2. bf16 HMMA GEMM (proven 430us version, verbatim) -------------
#define ROWB 144
#define STAGE_BYTES (2 * 128 * ROWB)   // 36864
#define GEMM_SMEM (2 * STAGE_BYTES)    // 73728
#define EPI_STRIDE 136

__global__ void __launch_bounds__(256)
gemm_bf16_kernel() {
    extern __shared__ __align__(16) char sm[];
    const int tid = threadIdx.x;
    const int wid = tid >> 5;
    const int lane = tid & 31;
    const int g = lane >> 2;
    const int tig = lane & 3;
    const int warpM = wid >> 2;
    const int warpN = wid & 3;
    const int mTile = blockIdx.x;
    const int nTile = blockIdx.y;

    const unsigned short* Ag = g_qnb + (size_t)mTile * 128 * DIMD;
    const unsigned short* Bg = g_knb + (size_t)nTile * 128 * DIMD;

    const uint32_t smBase = smem_u32(sm);
    const int cprow = tid >> 3;
    const int cpj = tid & 7;
    const uint32_t aOff = (uint32_t)((warpM * 64 + (lane & 15)) * ROWB + (lane >> 4) * 16);
    const uint32_t bOff = (uint32_t)(128 * ROWB +
                          (warpN * 32 + ((lane >> 4) & 1) * 8 + (lane & 7)) * ROWB +
                          ((lane >> 3) & 1) * 16);

    float acc[4][4][4];
#pragma unroll
    for (int mi = 0; mi < 4; mi++)
#pragma unroll
        for (int ni = 0; ni < 4; ni++)
#pragma unroll
            for (int q = 0; q < 4; q++) acc[mi][ni][q] = 0.f;

#pragma unroll
    for (int l = 0; l < 4; l++) {
        int row = cprow + l * 32;
        uint32_t so = (uint32_t)(row * ROWB + cpj * 16);
        cp16(smBase + so, Ag + (size_t)row * DIMD + cpj * 8);
        cp16(smBase + 128 * ROWB + so, Bg + (size_t)row * DIMD + cpj * 8);
    }
    CP_COMMIT();

#pragma unroll
    for (int kc = 0; kc < 4; kc++) {
        if (kc < 3) {
            uint32_t st = (uint32_t)(((kc + 1) & 1) * STAGE_BYTES);
#pragma unroll
            for (int l = 0; l < 4; l++) {
                int row = cprow + l * 32;
                uint32_t so = st + (uint32_t)(row * ROWB + cpj * 16);
                cp16(smBase + so, Ag + (size_t)row * DIMD + (kc + 1) * 64 + cpj * 8);
                cp16(smBase + 128 * ROWB + so, Bg + (size_t)row * DIMD + (kc + 1) * 64 + cpj * 8);
            }
            CP_COMMIT();
            CP_WAIT1();
        } else {
            CP_WAIT0();
        }
        __syncthreads();

        const uint32_t stA = smBase + (uint32_t)((kc & 1) * STAGE_BYTES) + aOff;
        const uint32_t stB = smBase + (uint32_t)((kc & 1) * STAGE_BYTES) + bOff;
#pragma unroll
        for (int ks = 0; ks < 4; ks++) {
            uint32_t af[4][4];
            uint32_t bf[4][2];
#pragma unroll
            for (int mi = 0; mi < 4; mi++)
                ldsm_x4(af[mi], stA + mi * (16 * ROWB) + ks * 32);
            {
                uint32_t t0[4], t1[4];
                ldsm_x4(t0, stB + ks * 32);
                ldsm_x4(t1, stB + 16 * ROWB + ks * 32);
                bf[0][0] = t0[0]; bf[0][1] = t0[1];
                bf[1][0] = t0[2]; bf[1][1] = t0[3];
                bf[2][0] = t1[0]; bf[2][1] = t1[1];
                bf[3][0] = t1[2]; bf[3][1] = t1[3];
            }
#pragma unroll
            for (int mi = 0; mi < 4; mi++)
#pragma unroll
                for (int ni = 0; ni < 4; ni++)
                    mma16816(acc[mi][ni], af[mi], bf[ni]);
        }
        __syncthreads();
    }

    unsigned short* esm = (unsigned short*)sm;
#pragma unroll
    for (int mi = 0; mi < 4; mi++) {
        int r0 = warpM * 64 + mi * 16 + g;
#pragma unroll
        for (int ni = 0; ni < 4; ni++) {
            int col = warpN * 32 + ni * 8 + tig * 2;
            unsigned p0 = __bfloat16_as_ushort(__float2bfloat16(acc[mi][ni][0])) |
                          ((unsigned)__bfloat16_as_ushort(__float2bfloat16(acc[mi][ni][1])) << 16);
            unsigned p1 = __bfloat16_as_ushort(__float2bfloat16(acc[mi][ni][2])) |
                          ((unsigned)__bfloat16_as_ushort(__float2bfloat16(acc[mi][ni][3])) << 16);
            *(unsigned*)&esm[r0 * EPI_STRIDE + col] = p0;
            *(unsigned*)&esm[(r0 + 8) * EPI_STRIDE + col] = p1;
        }
    }
    __syncthreads();
#pragma unroll
    for (int l = 0; l < 8; l++) {
        int t = tid + l * 256;
        int row = t >> 4;
        int cg = t & 15;
        uint4 v = *(const uint4*)&esm[row * EPI_STRIDE + cg * 8];
        *(uint4*)(g_simsb + (size_t)(mTile * 128 + row) * MMEM + nTile * 128 + cg * 8) = v;
    }
}

// ------------- 3. select: thresholded-histogram two-scan + exact rescore -------------
#define TPB 256
#define CAP 2048
#define NBIN 4096
#define MARGIN 0.01f
// encoded key for bf16 0.125 (0x3E00): positive -> key = bits | 0x8000 = 0xBE00
#define KTHR 0xBE00u

__global__ void __launch_bounds__(TPB)
select_kernel(const float* __restrict__ x, const int* __restrict__ y,
              const float* __restrict__ mk, const int* __restrict__ mem_vals,
              float* __restrict__ out) {
    __shared__ unsigned hist[NBIN];
    __shared__ unsigned candIdx[CAP];
    __shared__ float candVal[CAP];
    __shared__ unsigned char selFlag[CAP];
    __shared__ float sx[DIMD];
    __shared__ unsigned chunkSum[256];
    __shared__ float cls[NCLS];
    __shared__ int candCount;
    __shared__ int sBin, sLow;
    __shared__ float sMax;
    __shared__ unsigned sMaxIdx;
    __shared__ float expSum;
    __shared__ unsigned posK, negK;

    const int row = blockIdx.x;
    const int tid = threadIdx.x;
    const int wid = tid >> 5;
    const int lane = tid & 31;
    const uint4* s4 = (const uint4*)(g_simsb + (size_t)row * MMEM);
    const int yrow = y[row];

    for (int i = tid; i < NBIN; i += TPB) hist[i] = 0;
    for (int i = tid; i < NCLS; i += TPB) cls[i] = 0.f;
    if (tid == 0) {
        candCount = 0; sLow = 0; expSum = 0.f;
        posK = enc_f(-2.0f); negK = enc_f(-2.0f);
    }
    sx[tid] = x[(size_t)row * DIMD + tid] * g_rnx[row];
    __syncthreads();

    // ---- pass 1: histogram ONLY keys >= enc(0.125) (~3% of elements) ----
    for (int i = tid; i < MMEM / 8; i += TPB) {
        uint4 v = s4[i];
        unsigned w[4] = {v.x, v.y, v.z, v.w};
#pragma unroll
        for (int q = 0; q < 4; q++) {
            unsigned h0 = w[q] & 0xFFFFu;
            unsigned h1 = w[q] >> 16;
            unsigned k0 = (h0 & 0x8000u) ? (h0 ^ 0xFFFFu) : (h0 | 0x8000u);
            unsigned k1 = (h1 & 0x8000u) ? (h1 ^ 0xFFFFu) : (h1 | 0x8000u);
            if (k0 >= KTHR) atomicAdd(&hist[k0 >> 4], 1u);
            if (k1 >= KTHR) atomicAdd(&hist[k1 >> 4], 1u);
        }
    }
    __syncthreads();

    // guard: if fewer than KTOP elements were histogrammed, complete the
    // histogram with the below-threshold elements (exact-equivalent; never
    // taken on this distribution: E[count >= 0.125] ~ 3600 per row)
    {
        unsigned s = 0;
#pragma unroll
        for (int i = 0; i < NBIN / 256; i++) s += hist[tid * (NBIN / 256) + i];
        chunkSum[tid] = s;
        __syncthreads();
        if (tid == 0) {
            unsigned total = 0;
            for (int i = 0; i < 256; i++) total += chunkSum[i];
            sLow = (total < (unsigned)KTOP) ? 1 : 0;
        }
        __syncthreads();
        if (sLow) {
            for (int i = tid; i < MMEM / 8; i += TPB) {
                uint4 v = s4[i];
                unsigned w[4] = {v.x, v.y, v.z, v.w};
#pragma unroll
                for (int q = 0; q < 4; q++) {
                    unsigned h0 = w[q] & 0xFFFFu;
                    unsigned h1 = w[q] >> 16;
                    unsigned k0 = (h0 & 0x8000u) ? (h0 ^ 0xFFFFu) : (h0 | 0x8000u);
                    unsigned k1 = (h1 & 0x8000u) ? (h1 ^ 0xFFFFu) : (h1 | 0x8000u);
                    if (k0 < KTHR) atomicAdd(&hist[k0 >> 4], 1u);
                    if (k1 < KTHR) atomicAdd(&hist[k1 >> 4], 1u);
                }
            }
            __syncthreads();
            unsigned s2 = 0;
#pragma unroll
            for (int i = 0; i < NBIN / 256; i++) s2 += hist[tid * (NBIN / 256) + i];
            chunkSum[tid] = s2;
            __syncthreads();
        }
        if (tid == 0) {
            int run = 0, c = 255, per = NBIN / 256;
            for (; c > 0; c--) { if (run + (int)chunkSum[c] >= KTOP) break; run += (int)chunkSum[c]; }
            int b = c * per + per - 1;
            for (; b > c * per; b--) { if (run + (int)hist[b] >= KTOP) break; run += (int)hist[b]; }
            sBin = b;
        }
        __syncthreads();
    }
    float cutoff;
    {
        unsigned kb = ((unsigned)sBin) << 4;   // lowest key in selected bin
        unsigned hb = (kb & 0x8000u) ? (kb & 0x7FFFu) : ((~kb) & 0xFFFFu);
        cutoff = __uint_as_float(hb << 16) - MARGIN;
    }
    __syncthreads();

    // ---- pass 2: collect candidate indices ----
    for (int i = tid; i < MMEM / 8; i += TPB) {
        uint4 v = s4[i];
        unsigned w[4] = {v.x, v.y, v.z, v.w};
#pragma unroll
        for (int q = 0; q < 4; q++) {
            float f0 = __uint_as_float((w[q] & 0xFFFFu) << 16);
            float f1 = __uint_as_float(w[q] & 0xFFFF0000u);
            if (f0 >= cutoff) {
                int p = atomicAdd(&candCount, 1);
                if (p < CAP) candIdx[p] = (unsigned)(i * 8 + q * 2);
            }
            if (f1 >= cutoff) {
                int p = atomicAdd(&candCount, 1);
                if (p < CAP) candIdx[p] = (unsigned)(i * 8 + q * 2 + 1);
            }
        }
    }
    __syncthreads();
    const int nc = (candCount < CAP) ? candCount : CAP;

    // ---- exact fp32 rescore: one warp per candidate ----
    for (int c = wid; c < nc; c += TPB / 32) {
        unsigned idx = candIdx[c];
        const float4* kr = (const float4*)(mk + (size_t)idx * DIMD);
        float4 a = kr[lane];
        float4 b = kr[lane + 32];
        float s = a.x * sx[lane * 4 + 0] + a.y * sx[lane * 4 + 1]
                + a.z * sx[lane * 4 + 2] + a.w * sx[lane * 4 + 3]
                + b.x * sx[128 + lane * 4 + 0] + b.y * sx[128 + lane * 4 + 1]
                + b.z * sx[128 + lane * 4 + 2] + b.w * sx[128 + lane * 4 + 3];
#pragma unroll
        for (int o = 16; o; o >>= 1) s += __shfl_xor_sync(0xffffffffu, s, o);
        if (lane == 0) candVal[c] = s * g_rnk[idx];
    }
    __syncthreads();

    // ---- exact ranking (value desc, index asc) ----
    for (int c = tid; c < nc; c += TPB) {
        unsigned uc = enc_f(candVal[c]);
        unsigned ic = candIdx[c];
        int cnt = 0;
        for (int j = 0; j < nc; j++) {
            unsigned uj = enc_f(candVal[j]);
            cnt += (uj > uc) || (uj == uc && candIdx[j] < ic);
        }
        selFlag[c] = (cnt < KTOP) ? 1 : 0;
        if (cnt == 0) { sMax = candVal[c]; sMaxIdx = ic; }
    }
    __syncthreads();

    // ---- outputs ----
    const float smax = sMax;
    for (int c = tid; c < nc; c += TPB) {
        if (selFlag[c]) {
            float v = candVal[c];
            float e = expf(v - smax);
            atomicAdd(&expSum, e);
            int lbl = mem_vals[candIdx[c]];
            atomicAdd(&cls[lbl], e);
            unsigned uv = enc_f(v);
            if (lbl == yrow) atomicMax(&posK, uv);
            else             atomicMax(&negK, uv);
        }
    }
    __syncthreads();

    if (tid < NCLS) out[BATCH + row * NCLS + tid] = cls[tid] / expSum;
    if (tid == 0) {
        out[row] = (float)mem_vals[sMaxIdx];
        float sp = __uint_as_float((posK & 0x80000000u) ? (posK & 0x7fffffffu) : ~posK);
        float sn = __uint_as_float((negK & 0x80000000u) ? (negK & 0x7fffffffu) : ~negK);
        float tl = sn - sp + 0.1f;
        out[BATCH + BATCH * NCLS + row] = (tl > 0.f) ? tl : 0.f;
    }
}

// ------------- launch -------------
extern "C" void kernel_launch(void* const* d_in, const int* in_sizes, int n_in,
                              void* d_out, int out_size) {
    const float* x  = (const float*)d_in[0];
    const int*   y  = (const int*)d_in[1];
    const float* mk = (const float*)d_in[2];
    const int*   mv = (const int*)d_in[3];
    float* out = (float*)d_out;

    static int once = 0;
    if (!once) {
        cudaFuncSetAttribute(gemm_bf16_kernel, cudaFuncAttributeMaxDynamicSharedMemorySize, GEMM_SMEM);
        once = 1;
    }

    prep_kernel<<<(BATCH + MMEM + 7) / 8, 256>>>(x, mk);

    dim3 grid(4, MMEM / 128);
    gemm_bf16_kernel<<<grid, 256, GEMM_SMEM>>>();

    select_kernel<<<BATCH, TPB>>>(x, y, mk, mv, out);
}

// round 16
// speedup vs baseline: 1.2011x; 1.2011x over previous
#include <cuda_runtime.h>
#include <cuda_bf16.h>
#include <math.h>
#include <stdint.h>

#define BATCH 512
#define DIMD 256
#define MMEM 131072
#define NCLS 100
#define KTOP 256

// ------------- scratch globals (no allocation allowed) -------------
__device__ unsigned short g_simsb[(size_t)BATCH * MMEM];    // bf16 approx sims, 134MB
__device__ unsigned short g_qnb[BATCH * DIMD];              // bf16 normalized queries
__device__ unsigned short g_knb[(size_t)MMEM * DIMD];       // bf16 normalized keys, 67MB
__device__ float g_rnx[BATCH];
__device__ float g_rnk[MMEM];

// ------------- helpers -------------
__device__ __forceinline__ unsigned enc_f(float f) {
    unsigned u = __float_as_uint(f);
    return (u & 0x80000000u) ? ~u : (u | 0x80000000u);
}
__device__ __forceinline__ uint32_t smem_u32(const void* p) {
    uint32_t a;
    asm("{ .reg .u64 t; cvta.to.shared.u64 t, %1; cvt.u32.u64 %0, t; }" : "=r"(a) : "l"(p));
    return a;
}
__device__ __forceinline__ void cp16(uint32_t saddr, const void* g) {
    asm volatile("cp.async.cg.shared.global [%0], [%1], 16;" :: "r"(saddr), "l"(g));
}
#define CP_COMMIT() asm volatile("cp.async.commit_group;" ::: "memory")
#define CP_WAIT1()  asm volatile("cp.async.wait_group 1;" ::: "memory")
#define CP_WAIT0()  asm volatile("cp.async.wait_group 0;" ::: "memory")

__device__ __forceinline__ void ldsm_x4(uint32_t* r, uint32_t addr) {
    asm volatile("ldmatrix.sync.aligned.m8n8.x4.shared.b16 {%0,%1,%2,%3}, [%4];"
                 : "=r"(r[0]), "=r"(r[1]), "=r"(r[2]), "=r"(r[3]) : "r"(addr));
}
__device__ __forceinline__ void mma16816(float* d, const uint32_t* a, const uint32_t* b) {
    asm volatile(
        "mma.sync.aligned.m16n8k16.row.col.f32.bf16.bf16.f32 "
        "{%0,%1,%2,%3}, {%4,%5,%6,%7}, {%8,%9}, {%0,%1,%2,%3};"
        : "+f"(d[0]), "+f"(d[1]), "+f"(d[2]), "+f"(d[3])
        : "r"(a[0]), "r"(a[1]), "r"(a[2]), "r"(a[3]), "r"(b[0]), "r"(b[1]));
}

// ------------- 1. prep: reciprocal norms + normalized bf16 conversion -------------
__global__ void prep_kernel(const float* __restrict__ x, const float* __restrict__ mk) {
    int warp = (blockIdx.x * blockDim.x + threadIdx.x) >> 5;
    int lane = threadIdx.x & 31;
    if (warp >= BATCH + MMEM) return;
    bool isX = (warp < BATCH);
    int row = isX ? warp : (warp - BATCH);
    const float* ptr = isX ? (x + (size_t)row * DIMD) : (mk + (size_t)row * DIMD);
    const float4* p4 = (const float4*)ptr;
    float4 v0 = p4[lane];
    float4 v1 = p4[lane + 32];
    float s = v0.x * v0.x + v0.y * v0.y + v0.z * v0.z + v0.w * v0.w
            + v1.x * v1.x + v1.y * v1.y + v1.z * v1.z + v1.w * v1.w;
#pragma unroll
    for (int o = 16; o; o >>= 1) s += __shfl_xor_sync(0xffffffffu, s, o);
    float rn = 1.0f / (sqrtf(s) + 1e-12f);
    rn = __shfl_sync(0xffffffffu, rn, 0);
    if (lane == 0) {
        if (isX) g_rnx[row] = rn; else g_rnk[row] = rn;
    }
    unsigned short* dst = isX ? (g_qnb + (size_t)row * DIMD) : (g_knb + (size_t)row * DIMD);
    {
        unsigned a = __bfloat16_as_ushort(__float2bfloat16(v0.x * rn)) |
                     ((unsigned)__bfloat16_as_ushort(__float2bfloat16(v0.y * rn)) << 16);
        unsigned b = __bfloat16_as_ushort(__float2bfloat16(v0.z * rn)) |
                     ((unsigned)__bfloat16_as_ushort(__float2bfloat16(v0.w * rn)) << 16);
        *(uint2*)(dst + lane * 4) = make_uint2(a, b);
    }
    {
        unsigned a = __bfloat16_as_ushort(__float2bfloat16(v1.x * rn)) |
                     ((unsigned)__bfloat16_as_ushort(__float2bfloat16(v1.y * rn)) << 16);
        unsigned b = __bfloat16_as_ushort(__float2bfloat16(v1.z * rn)) |
                     ((unsigned)__bfloat16_as_ushort(__float2bfloat16(v1.w * rn)) << 16);
        *(uint2*)(dst + (lane + 32) * 4) = make_uint2(a, b);
    }
}

// ------------- 2. bf16 HMMA GEMM (proven 430us version, verbatim) -------------
#define ROWB 144
#define STAGE_BYTES (2 * 128 * ROWB)   // 36864
#define GEMM_SMEM (2 * STAGE_BYTES)    // 73728
#define EPI_STRIDE 136

__global__ void __launch_bounds__(256)
gemm_bf16_kernel() {
    extern __shared__ __align__(16) char sm[];
    const int tid = threadIdx.x;
    const int wid = tid >> 5;
    const int lane = tid & 31;
    const int g = lane >> 2;
    const int tig = lane & 3;
    const int warpM = wid >> 2;
    const int warpN = wid & 3;
    const int mTile = blockIdx.x;
    const int nTile = blockIdx.y;

    const unsigned short* Ag = g_qnb + (size_t)mTile * 128 * DIMD;
    const unsigned short* Bg = g_knb + (size_t)nTile * 128 * DIMD;

    const uint32_t smBase = smem_u32(sm);
    const int cprow = tid >> 3;
    const int cpj = tid & 7;
    const uint32_t aOff = (uint32_t)((warpM * 64 + (lane & 15)) * ROWB + (lane >> 4) * 16);
    const uint32_t bOff = (uint32_t)(128 * ROWB +
                          (warpN * 32 + ((lane >> 4) & 1) * 8 + (lane & 7)) * ROWB +
                          ((lane >> 3) & 1) * 16);

    float acc[4][4][4];
#pragma unroll
    for (int mi = 0; mi < 4; mi++)
#pragma unroll
        for (int ni = 0; ni < 4; ni++)
#pragma unroll
            for (int q = 0; q < 4; q++) acc[mi][ni][q] = 0.f;

#pragma unroll
    for (int l = 0; l < 4; l++) {
        int row = cprow + l * 32;
        uint32_t so = (uint32_t)(row * ROWB + cpj * 16);
        cp16(smBase + so, Ag + (size_t)row * DIMD + cpj * 8);
        cp16(smBase + 128 * ROWB + so, Bg + (size_t)row * DIMD + cpj * 8);
    }
    CP_COMMIT();

#pragma unroll
    for (int kc = 0; kc < 4; kc++) {
        if (kc < 3) {
            uint32_t st = (uint32_t)(((kc + 1) & 1) * STAGE_BYTES);
#pragma unroll
            for (int l = 0; l < 4; l++) {
                int row = cprow + l * 32;
                uint32_t so = st + (uint32_t)(row * ROWB + cpj * 16);
                cp16(smBase + so, Ag + (size_t)row * DIMD + (kc + 1) * 64 + cpj * 8);
                cp16(smBase + 128 * ROWB + so, Bg + (size_t)row * DIMD + (kc + 1) * 64 + cpj * 8);
            }
            CP_COMMIT();
            CP_WAIT1();
        } else {
            CP_WAIT0();
        }
        __syncthreads();

        const uint32_t stA = smBase + (uint32_t)((kc & 1) * STAGE_BYTES) + aOff;
        const uint32_t stB = smBase + (uint32_t)((kc & 1) * STAGE_BYTES) + bOff;
#pragma unroll
        for (int ks = 0; ks < 4; ks++) {
            uint32_t af[4][4];
            uint32_t bf[4][2];
#pragma unroll
            for (int mi = 0; mi < 4; mi++)
                ldsm_x4(af[mi], stA + mi * (16 * ROWB) + ks * 32);
            {
                uint32_t t0[4], t1[4];
                ldsm_x4(t0, stB + ks * 32);
                ldsm_x4(t1, stB + 16 * ROWB + ks * 32);
                bf[0][0] = t0[0]; bf[0][1] = t0[1];
                bf[1][0] = t0[2]; bf[1][1] = t0[3];
                bf[2][0] = t1[0]; bf[2][1] = t1[1];
                bf[3][0] = t1[2]; bf[3][1] = t1[3];
            }
#pragma unroll
            for (int mi = 0; mi < 4; mi++)
#pragma unroll
                for (int ni = 0; ni < 4; ni++)
                    mma16816(acc[mi][ni], af[mi], bf[ni]);
        }
        __syncthreads();
    }

    unsigned short* esm = (unsigned short*)sm;
#pragma unroll
    for (int mi = 0; mi < 4; mi++) {
        int r0 = warpM * 64 + mi * 16 + g;
#pragma unroll
        for (int ni = 0; ni < 4; ni++) {
            int col = warpN * 32 + ni * 8 + tig * 2;
            unsigned p0 = __bfloat16_as_ushort(__float2bfloat16(acc[mi][ni][0])) |
                          ((unsigned)__bfloat16_as_ushort(__float2bfloat16(acc[mi][ni][1])) << 16);
            unsigned p1 = __bfloat16_as_ushort(__float2bfloat16(acc[mi][ni][2])) |
                          ((unsigned)__bfloat16_as_ushort(__float2bfloat16(acc[mi][ni][3])) << 16);
            *(unsigned*)&esm[r0 * EPI_STRIDE + col] = p0;
            *(unsigned*)&esm[(r0 + 8) * EPI_STRIDE + col] = p1;
        }
    }
    __syncthreads();
#pragma unroll
    for (int l = 0; l < 8; l++) {
        int t = tid + l * 256;
        int row = t >> 4;
        int cg = t & 15;
        uint4 v = *(const uint4*)&esm[row * EPI_STRIDE + cg * 8];
        *(uint4*)(g_simsb + (size_t)(mTile * 128 + row) * MMEM + nTile * 128 + cg * 8) = v;
    }
}

// ------------- 3. select: r4 algorithm, 512 threads for scan occupancy -------------
#define TPB 512
#define CAP 2048
#define NBIN 4096
#define MARGIN 0.01f

__global__ void __launch_bounds__(TPB)
select_kernel(const float* __restrict__ x, const int* __restrict__ y,
              const float* __restrict__ mk, const int* __restrict__ mem_vals,
              float* __restrict__ out) {
    __shared__ unsigned hist[NBIN];
    __shared__ unsigned candIdx[CAP];
    __shared__ float candVal[CAP];
    __shared__ unsigned char selFlag[CAP];
    __shared__ float sx[DIMD];
    __shared__ unsigned chunkSum[TPB];
    __shared__ float cls[NCLS];
    __shared__ int candCount;
    __shared__ int sBin;
    __shared__ float sMax;
    __shared__ unsigned sMaxIdx;
    __shared__ float expSum;
    __shared__ unsigned posK, negK;

    const int row = blockIdx.x;
    const int tid = threadIdx.x;
    const int wid = tid >> 5;
    const int lane = tid & 31;
    const uint4* s4 = (const uint4*)(g_simsb + (size_t)row * MMEM);
    const int yrow = y[row];

    for (int i = tid; i < NBIN; i += TPB) hist[i] = 0;
    for (int i = tid; i < NCLS; i += TPB) cls[i] = 0.f;
    if (tid == 0) {
        candCount = 0; expSum = 0.f;
        posK = enc_f(-2.0f); negK = enc_f(-2.0f);
    }
    if (tid < DIMD) sx[tid] = x[(size_t)row * DIMD + tid] * g_rnx[row];
    __syncthreads();

    // pass 1: 12-bit histogram of monotonically-encoded bf16 keys
    for (int i = tid; i < MMEM / 8; i += TPB) {
        uint4 v = s4[i];
        unsigned w[4] = {v.x, v.y, v.z, v.w};
#pragma unroll
        for (int q = 0; q < 4; q++) {
            unsigned h0 = w[q] & 0xFFFFu;
            unsigned h1 = w[q] >> 16;
            unsigned k0 = (h0 & 0x8000u) ? (h0 ^ 0xFFFFu) : (h0 | 0x8000u);
            unsigned k1 = (h1 & 0x8000u) ? (h1 ^ 0xFFFFu) : (h1 | 0x8000u);
            atomicAdd(&hist[k0 >> 4], 1u);
            atomicAdd(&hist[k1 >> 4], 1u);
        }
    }
    __syncthreads();

    // find bin containing the 256th largest (approx); 512 chunks of 8 bins
    {
        unsigned s = 0;
#pragma unroll
        for (int i = 0; i < NBIN / TPB; i++) s += hist[tid * (NBIN / TPB) + i];
        chunkSum[tid] = s;
        __syncthreads();
        if (tid == 0) {
            int run = 0, c = TPB - 1, per = NBIN / TPB;
            for (; c > 0; c--) { if (run + (int)chunkSum[c] >= KTOP) break; run += (int)chunkSum[c]; }
            int b = c * per + per - 1;
            for (; b > c * per; b--) { if (run + (int)hist[b] >= KTOP) break; run += (int)hist[b]; }
            sBin = b;
        }
        __syncthreads();
    }
    float cutoff;
    {
        unsigned kb = ((unsigned)sBin) << 4;   // lowest key in selected bin
        unsigned hb = (kb & 0x8000u) ? (kb & 0x7FFFu) : ((~kb) & 0xFFFFu);
        cutoff = __uint_as_float(hb << 16) - MARGIN;
    }
    __syncthreads();

    // pass 2: collect candidate indices
    for (int i = tid; i < MMEM / 8; i += TPB) {
        uint4 v = s4[i];
        unsigned w[4] = {v.x, v.y, v.z, v.w};
#pragma unroll
        for (int q = 0; q < 4; q++) {
            float f0 = __uint_as_float((w[q] & 0xFFFFu) << 16);
            float f1 = __uint_as_float(w[q] & 0xFFFF0000u);
            if (f0 >= cutoff) {
                int p = atomicAdd(&candCount, 1);
                if (p < CAP) candIdx[p] = (unsigned)(i * 8 + q * 2);
            }
            if (f1 >= cutoff) {
                int p = atomicAdd(&candCount, 1);
                if (p < CAP) candIdx[p] = (unsigned)(i * 8 + q * 2 + 1);
            }
        }
    }
    __syncthreads();
    const int nc = (candCount < CAP) ? candCount : CAP;

    // exact fp32 rescore: one warp per candidate (16 warps)
    for (int c = wid; c < nc; c += TPB / 32) {
        unsigned idx = candIdx[c];
        const float4* kr = (const float4*)(mk + (size_t)idx * DIMD);
        float4 a = kr[lane];
        float4 b = kr[lane + 32];
        float s = a.x * sx[lane * 4 + 0] + a.y * sx[lane * 4 + 1]
                + a.z * sx[lane * 4 + 2] + a.w * sx[lane * 4 + 3]
                + b.x * sx[128 + lane * 4 + 0] + b.y * sx[128 + lane * 4 + 1]
                + b.z * sx[128 + lane * 4 + 2] + b.w * sx[128 + lane * 4 + 3];
#pragma unroll
        for (int o = 16; o; o >>= 1) s += __shfl_xor_sync(0xffffffffu, s, o);
        if (lane == 0) candVal[c] = s * g_rnk[idx];
    }
    __syncthreads();

    // exact ranking (value desc, index asc): rank < 256 selected
    for (int c = tid; c < nc; c += TPB) {
        unsigned uc = enc_f(candVal[c]);
        unsigned ic = candIdx[c];
        int cnt = 0;
        for (int j = 0; j < nc; j++) {
            unsigned uj = enc_f(candVal[j]);
            cnt += (uj > uc) || (uj == uc && candIdx[j] < ic);
        }
        selFlag[c] = (cnt < KTOP) ? 1 : 0;
        if (cnt == 0) { sMax = candVal[c]; sMaxIdx = ic; }
    }
    __syncthreads();

    // softmax class sums + pos/neg maxima over selected set
    const float smax = sMax;
    for (int c = tid; c < nc; c += TPB) {
        if (selFlag[c]) {
            float v = candVal[c];
            float e = expf(v - smax);
            atomicAdd(&expSum, e);
            int lbl = mem_vals[candIdx[c]];
            atomicAdd(&cls[lbl], e);
            unsigned uv = enc_f(v);
            if (lbl == yrow) atomicMax(&posK, uv);
            else             atomicMax(&negK, uv);
        }
    }
    __syncthreads();

    if (tid < NCLS) out[BATCH + row * NCLS + tid] = cls[tid] / expSum;
    if (tid == 0) {
        out[row] = (float)mem_vals[sMaxIdx];
        float sp = __uint_as_float((posK & 0x80000000u) ? (posK & 0x7fffffffu) : ~posK);
        float sn = __uint_as_float((negK & 0x80000000u) ? (negK & 0x7fffffffu) : ~negK);
        float tl = sn - sp + 0.1f;
        out[BATCH + BATCH * NCLS + row] = (tl > 0.f) ? tl : 0.f;
    }
}

// ------------- launch -------------
extern "C" void kernel_launch(void* const* d_in, const int* in_sizes, int n_in,
                              void* d_out, int out_size) {
    const float* x  = (const float*)d_in[0];
    const int*   y  = (const int*)d_in[1];
    const float* mk = (const float*)d_in[2];
    const int*   mv = (const int*)d_in[3];
    float* out = (float*)d_out;

    static int once = 0;
    if (!once) {
        cudaFuncSetAttribute(gemm_bf16_kernel, cudaFuncAttributeMaxDynamicSharedMemorySize, GEMM_SMEM);
        once = 1;
    }

    prep_kernel<<<(BATCH + MMEM + 7) / 8, 256>>>(x, mk);

    dim3 grid(4, MMEM / 128);
    gemm_bf16_kernel<<<grid, 256, GEMM_SMEM>>>();

    select_kernel<<<BATCH, TPB>>>(x, y, mk, mv, out);
}